// round 1
// baseline (speedup 1.0000x reference)
#include <cuda_runtime.h>

// x: (B=64, NU=32, IC=256, UNIT=128) fp32, contiguous.
// Reference reinterprets flat buffer as (B, IC, NU, UNIT):
//   u_hat[b,i,j,u] = x_flat[b*1048576 + i*4096 + j*128 + u]
// s[b,j,u] = (1/256) * sum_i u_hat[b,i,j,u]; then squash over u (128 elems).
// Output: (B, NU, UNIT) = 262144 fp32.
//
// One warp per (b,j) group: 2048 warps total. Lane l owns float4 at u=4l.
// 256 strided float4 loads per lane (stride 4096 floats = 1024 float4),
// unrolled x8 for MLP. Warp shuffle reduction for mag_sq. Pure HBM stream.

static constexpr int IC        = 256;
static constexpr int GROUPS    = 64 * 32;          // B * NU
static constexpr int STRIDE4   = 4096 / 4;         // i-stride in float4 units
static constexpr int THREADS   = 256;              // 8 warps/block
static constexpr int BLOCKS    = GROUPS * 32 / THREADS;  // 256 blocks

__global__ __launch_bounds__(THREADS)
void capsule_squash_kernel(const float4* __restrict__ x4,
                           float4* __restrict__ out4) {
    const int gwarp = (blockIdx.x * THREADS + threadIdx.x) >> 5;  // group id
    const int lane  = threadIdx.x & 31;

    // group = b*32 + j ; base float index = b*1048576 + j*128 + lane*4
    const int b = gwarp >> 5;
    const int j = gwarp & 31;
    const int base4 = b * (1048576 / 4) + j * (128 / 4) + lane;

    float4 s = make_float4(0.f, 0.f, 0.f, 0.f);
#pragma unroll 8
    for (int i = 0; i < IC; i++) {
        float4 v = __ldg(&x4[base4 + i * STRIDE4]);
        s.x += v.x; s.y += v.y; s.z += v.z; s.w += v.w;
    }

    const float c = 1.0f / 256.0f;
    s.x *= c; s.y *= c; s.z *= c; s.w *= c;

    // mag_sq over the 128-element unit dim (warp-wide)
    float sq = s.x * s.x + s.y * s.y + s.z * s.z + s.w * s.w;
#pragma unroll
    for (int off = 16; off > 0; off >>= 1)
        sq += __shfl_xor_sync(0xffffffffu, sq, off);

    const float mag   = sqrtf(sq);
    const float scale = sq / (1.0f + sq) / (mag + 1e-5f);

    float4 o = make_float4(s.x * scale, s.y * scale, s.z * scale, s.w * scale);
    out4[gwarp * 32 + lane] = o;
}

extern "C" void kernel_launch(void* const* d_in, const int* in_sizes, int n_in,
                              void* d_out, int out_size) {
    const float4* x4 = (const float4*)d_in[0];
    float4* out4 = (float4*)d_out;
    capsule_squash_kernel<<<BLOCKS, THREADS>>>(x4, out4);
}

// round 2
// speedup vs baseline: 1.4653x; 1.4653x over previous
#include <cuda_runtime.h>

// x: (B=64, NU=32, IC=256, UNIT=128) fp32, contiguous.
// Reference reinterprets flat buffer as (B, IC, NU, UNIT):
//   u_hat[b,i,j,u] = x_flat[b*1048576 + i*4096 + j*128 + u]
// s[b,j,u] = (1/256) * sum_i u_hat[b,i,j,u]; then squash over u (128 elems).
// Output: (B, NU, UNIT) = 262144 fp32.
//
// R2: one BLOCK (8 warps) per (b,j) group -> 2048 blocks, 16384 warps
// (8x round-1 concurrency; occ was 20.9%, latency-bound at DRAM=52.7%).
// Warp w sums i-rows [w*32, w*32+32); lane l owns float4 at u=4*l.
// Partials reduced via smem; warp 0 does the squash + store.

static constexpr int IC       = 256;
static constexpr int GROUPS   = 64 * 32;        // B * NU = 2048 blocks
static constexpr int STRIDE4  = 4096 / 4;       // i-stride in float4 units
static constexpr int THREADS  = 256;            // 8 warps/block
static constexpr int IC_PER_W = IC / 8;         // 32 rows per warp

__global__ __launch_bounds__(THREADS)
void capsule_squash_kernel(const float4* __restrict__ x4,
                           float4* __restrict__ out4) {
    const int g    = blockIdx.x;                // group = b*32 + j
    const int warp = threadIdx.x >> 5;
    const int lane = threadIdx.x & 31;

    const int b = g >> 5;
    const int j = g & 31;
    // base float4 index for this thread's first row
    const int base4 = b * (1048576 / 4) + j * (128 / 4) + lane
                    + (warp * IC_PER_W) * STRIDE4;

    float4 s = make_float4(0.f, 0.f, 0.f, 0.f);
#pragma unroll 8
    for (int i = 0; i < IC_PER_W; i++) {
        float4 v = __ldg(&x4[base4 + i * STRIDE4]);
        s.x += v.x; s.y += v.y; s.z += v.z; s.w += v.w;
    }

    __shared__ float4 part[8][32];
    part[warp][lane] = s;
    __syncthreads();

    if (warp == 0) {
        float4 t = part[0][lane];
#pragma unroll
        for (int w = 1; w < 8; w++) {
            float4 p = part[w][lane];
            t.x += p.x; t.y += p.y; t.z += p.z; t.w += p.w;
        }
        const float c = 1.0f / 256.0f;
        t.x *= c; t.y *= c; t.z *= c; t.w *= c;

        // mag_sq over the 128-element unit dim (warp-wide)
        float sq = t.x * t.x + t.y * t.y + t.z * t.z + t.w * t.w;
#pragma unroll
        for (int off = 16; off > 0; off >>= 1)
            sq += __shfl_xor_sync(0xffffffffu, sq, off);

        const float mag   = sqrtf(sq);
        const float scale = sq / (1.0f + sq) / (mag + 1e-5f);

        out4[g * 32 + lane] = make_float4(t.x * scale, t.y * scale,
                                          t.z * scale, t.w * scale);
    }
}

extern "C" void kernel_launch(void* const* d_in, const int* in_sizes, int n_in,
                              void* d_out, int out_size) {
    const float4* x4 = (const float4*)d_in[0];
    float4* out4 = (float4*)d_out;
    capsule_squash_kernel<<<GROUPS, THREADS>>>(x4, out4);
}